// round 13
// baseline (speedup 1.0000x reference)
#include <cuda_runtime.h>
#include <math.h>

// AMPS fast log-prob, v10: 64-step chunks, f32x2 state, j-contiguous duplicated staging.
//   chain(n, bs): v = e0^T * Prod_{m=0..n} A(n,m,bs);  A = plane-selected 4x4 of tri_up[n(n+1)/2+m]
//   logits[n+1][bs][p] = v . diag[n+1][:,p];  out[bs] = sum_n logsoftmax(logits[n])[sel]
// Main: lane = (chunk g, sample bs); P2[ip][k] = (P[2ip][k], P[2ip+1][k]) packed f32x2.
//   Step: for j: 2 LDS.128 (column j, pre-duplicated) -> 8 fma.f32x2.  No FSEL, no shfl.
// Combine: v = row0(P_0) @ P_1 @ ...; fused lse; last block reduces (atomic counter).

#define NN    1024
#define NCH   1023
#define FULLM 0xffffffffu
#define TT    4
#define NCID  8688
#define NBLK  543      // ceil(8688 / 16)
#define CELL  88       // floats per (t,g) cell
#define POFF  36       // plane1 float offset within cell

typedef unsigned long long ull;

__device__ __forceinline__ ull fma2(ull a, ull b, ull c) {
    ull d; asm("fma.rn.f32x2 %0, %1, %2, %3;" : "=l"(d) : "l"(a), "l"(b), "l"(c)); return d;
}
__device__ __forceinline__ ull mul2(ull a, ull b) {
    ull d; asm("mul.rn.f32x2 %0, %1, %2;" : "=l"(d) : "l"(a), "l"(b)); return d;
}
__device__ __forceinline__ float lo2(ull a) { float2 f; asm("mov.b64 {%0,%1}, %2;" : "=f"(f.x), "=f"(f.y) : "l"(a)); return f.x; }
__device__ __forceinline__ float hi2(ull a) { float2 f; asm("mov.b64 {%0,%1}, %2;" : "=f"(f.x), "=f"(f.y) : "l"(a)); return f.y; }

__device__ float g_M[NCID * 128];        // [cid][bs*16 + i*4 + j]
__device__ float g_contrib[8 * 1024];    // [bs][pos]
__device__ unsigned g_sel[NN];           // bit bs = plane (0 if data!=0 else 1)
__device__ int g_count;

__constant__ int c_off[17] = {0,1023,1982,2877,3708,4475,5178,5817,6392,6903,
                              7350,7733,8052,8307,8498,8625,8688};

// ---------------- prep: selector bits + counter reset ----------------
__global__ void amps_prep(const float* __restrict__ data) {
    int m = blockIdx.x * 128 + threadIdx.x;
    if (m < NN) {
        unsigned s = 0;
#pragma unroll
        for (int b = 0; b < 8; b++) s |= ((data[b * NN + m] != 0.0f) ? 0u : 1u) << b;
        g_sel[m] = s;
    }
    if (m == 0) g_count = 0;
}

// ---------------- main: 64-step chunk products ----------------
__global__ __launch_bounds__(128, 5) void amps_main(const float* __restrict__ tri) {
    __shared__ unsigned ssel[NN];
    __shared__ float sbuf[4][TT * 4 * CELL];   // [warp][(t*4+g)*CELL]

    const int tid = threadIdx.x, warp = tid >> 5, lane = tid & 31;
    const int g = lane >> 3, bs = lane & 7;

    for (int m = tid; m < NN; m += 128) ssel[m] = g_sel[m];
    __syncthreads();

    const float4* tri4 = (const float4*)tri;
    float* wb = sbuf[warp];

    const int cid = (blockIdx.x * 4 + warp) * 4 + g;
    const bool valid = (cid < NCID);
    const int cc = valid ? cid : 0;
    int c = 0;
#pragma unroll
    for (int j = 1; j < 16; j++) if (cc >= c_off[j]) c = j;
    const int n = 64 * c + (cc - c_off[c]);
    const int mS = 64 * c;
    const int steps = min(n, mS + 63) - mS + 1;
    const int ws = __reduce_max_sync(FULLM, steps);
    const size_t t0 = (size_t)n * (n + 1) / 2;
    const float4* base = tri4 + (t0 + mS) * 8;
    const int sc = steps - 1;

    // P2[ip*4+k] = (P[2ip][k], P[2ip+1][k]); init identity
    ull P2[8];
    P2[0] = 0x000000003f800000ULL; P2[1] = 0x3f80000000000000ULL; P2[2] = 0; P2[3] = 0;
    P2[4] = 0; P2[5] = 0; P2[6] = 0x000000003f800000ULL; P2[7] = 0x3f80000000000000ULL;

    // this lane's float4 = (a[l][r0][p0], a[l][r0][p1], a[l][r0+1][p0], a[l][r0+1][p1])
    const int l = bs >> 1, r0 = (bs & 1) * 2;
    const int soA = r0 * 8 + l * 2;          // dst for (p0, j=r0)
    const int soB = (r0 + 1) * 8 + l * 2;    // dst for (p0, j=r0+1)

    float4 r[TT];
#pragma unroll
    for (int t = 0; t < TT; t++) r[t] = __ldg(base + (size_t)min(t, sc) * 8 + bs);

    for (int st = 0; st < ws; st += TT) {
        __syncwarp();
#pragma unroll
        for (int t = 0; t < TT; t++) {
            float* cell = wb + (t * 4 + g) * CELL;
            float4 w = r[t];
            *(float2*)(cell + soA)        = make_float2(w.x, w.x);
            *(float2*)(cell + POFF + soA) = make_float2(w.y, w.y);
            *(float2*)(cell + soB)        = make_float2(w.z, w.z);
            *(float2*)(cell + POFF + soB) = make_float2(w.w, w.w);
        }
        __syncwarp();
        if (st + TT < ws) {
#pragma unroll
            for (int t = 0; t < TT; t++)
                r[t] = __ldg(base + (size_t)min(st + TT + t, sc) * 8 + bs);
        }
#pragma unroll
        for (int t = 0; t < TT; t++) {
            const int s = st + t;
            const int p = (ssel[mS + s] >> bs) & 1;
            const float4* ap = (const float4*)(wb + (t * 4 + g) * CELL + p * POFF);
            if (s < steps) {
                ull q[8];
#pragma unroll
                for (int j = 0; j < 4; j++) {
                    float4 c01 = ap[j * 2];       // (dup a0j, dup a1j)
                    float4 c23 = ap[j * 2 + 1];   // (dup a2j, dup a3j)
                    ull a0 = *(const ull*)&c01.x;
                    ull a1 = *(const ull*)&c01.z;
                    ull a2 = *(const ull*)&c23.x;
                    ull a3 = *(const ull*)&c23.z;
                    q[j]     = fma2(P2[0], a0, fma2(P2[1], a1, fma2(P2[2], a2, mul2(P2[3], a3))));
                    q[4 + j] = fma2(P2[4], a0, fma2(P2[5], a1, fma2(P2[6], a2, mul2(P2[7], a3))));
                }
#pragma unroll
                for (int k = 0; k < 4; k++) { P2[k] = q[k]; P2[4 + k] = q[4 + k]; }
            }
        }
    }
    if (valid) {
        float4* dst = (float4*)&g_M[(size_t)cid * 128 + bs * 16];
        dst[0] = make_float4(lo2(P2[0]), lo2(P2[1]), lo2(P2[2]), lo2(P2[3]));
        dst[1] = make_float4(hi2(P2[0]), hi2(P2[1]), hi2(P2[2]), hi2(P2[3]));
        dst[2] = make_float4(lo2(P2[4]), lo2(P2[5]), lo2(P2[6]), lo2(P2[7]));
        dst[3] = make_float4(hi2(P2[4]), hi2(P2[5]), hi2(P2[6]), hi2(P2[7]));
    }
}

// ---------------- combine: v = row0(P_0) @ P_1 @ ...; lse; fused last-block reduce ----------------
__global__ __launch_bounds__(256) void amps_combine(const float* __restrict__ data,
                                                    const float* __restrict__ diag,
                                                    float* __restrict__ out) {
    const int warp = threadIdx.x >> 5, lane = threadIdx.x & 31;
    const int bs = lane >> 2, rr = lane & 3;
    const int n = blockIdx.x * 8 + warp;

    if (n < NCH) {
        float4 vv = *(const float4*)&g_M[(size_t)n * 128 + bs * 16];  // cid(n,0)=n, row 0
        float v0 = vv.x, v1 = vv.y, v2 = vv.z, v3 = vv.w;

        const int nch = (n >> 6) + 1;
        for (int c = 1; c < nch; c++) {
            const int cid = c_off[c] + n - 64 * c;
            const float* Mb = &g_M[(size_t)cid * 128 + bs * 16];
            float nv = v0 * Mb[rr] + v1 * Mb[4 + rr] + v2 * Mb[8 + rr] + v3 * Mb[12 + rr];
            int qb = lane & ~3;
            v0 = __shfl_sync(FULLM, nv, qb);
            v1 = __shfl_sync(FULLM, nv, qb + 1);
            v2 = __shfl_sync(FULLM, nv, qb + 2);
            v3 = __shfl_sync(FULLM, nv, qb + 3);
        }
        const float* dg = diag + (size_t)(n + 1) * 8;
        const int rp = rr & 1;
        float x = v0 * dg[rp] + v1 * dg[2 + rp] + v2 * dg[4 + rp] + v3 * dg[6 + rp];
        float x1 = __shfl_sync(FULLM, x, (lane & ~3) + 1);
        if (rr == 0) {
            float x0 = x;
            float mx = fmaxf(x0, x1);
            float lse = mx + log1pf(expf(-fabsf(x0 - x1)));
            bool p1 = (data[bs * NN + (n + 1)] == 0.0f);
            g_contrib[bs * 1024 + n + 1] = (p1 ? x1 : x0) - lse;
        }
    }

    // ---- last block reduces everything (deterministic order) ----
    __shared__ int sdone;
    __threadfence();
    __syncthreads();
    if (threadIdx.x == 0) sdone = (atomicAdd(&g_count, 1) == gridDim.x - 1) ? 1 : 0;
    __syncthreads();
    if (!sdone) return;
    __threadfence();

    const int rbs = threadIdx.x >> 5;   // warp = sample
    const int rl = threadIdx.x & 31;
    float acc = 0.0f;
    const float4* cb = (const float4*)(g_contrib + rbs * 1024);
#pragma unroll
    for (int it = 0; it < 8; it++) {
        float4 v = cb[it * 32 + rl];
        if (it == 0 && rl == 0) {
            float x0 = diag[0], x1 = diag[1];
            float mx = fmaxf(x0, x1);
            float lse = mx + log1pf(expf(-fabsf(x0 - x1)));
            v.x = ((data[rbs * NN] == 0.0f) ? x1 : x0) - lse;  // n=0 term
        }
        acc += v.x + v.y + v.z + v.w;
    }
#pragma unroll
    for (int o = 16; o; o >>= 1) acc += __shfl_xor_sync(FULLM, acc, o);
    if (rl == 0) out[rbs] = acc;
}

extern "C" void kernel_launch(void* const* d_in, const int* in_sizes, int n_in,
                              void* d_out, int out_size) {
    const float* data = (const float*)d_in[0];
    const float* tri  = (const float*)d_in[1];
    const float* diag = (const float*)d_in[2];
    float* out = (float*)d_out;

    amps_prep<<<8, 128>>>(data);
    amps_main<<<NBLK, 128>>>(tri);
    amps_combine<<<128, 256>>>(data, diag, out);
}

// round 14
// speedup vs baseline: 1.2551x; 1.2551x over previous
#include <cuda_runtime.h>
#include <math.h>

// AMPS fast log-prob, v11: R6 proven main (scalar FSEL path, 26.4us) + fused combine/reduce tail.
//   chain(n, bs): v = e0^T * Prod_{m=0..n} A(n,m,bs);  A = plane-selected 4x4 of tri_up[n(n+1)/2+m]
//   logits[n+1][bs][p] = v . diag[n+1][:,p];  out[bs] = sum_n logsoftmax(logits[n])[sel]
// Main: work unit = 64-step 4x4 chunk product (m in [64c, 64c+63]), lane = (chunk g, sample bs),
//       full P[16] in regs, A distributed via warp-private smem tiles (no shfl).
// Combine: v = row0(P_0) @ P_1 @ ...; fused log-softmax; last block reduces (atomic counter).

#define NN    1024
#define NCH   1023
#define SMCH  64
#define FULLM 0xffffffffu
#define TT    8
#define NCID  8688
#define NBLK  272     // ceil(8688/4/8)

__device__ float g_M[NCID * 128];         // [cid][bs*16 + i*4 + j]
__device__ float g_contrib[8 * 1024];     // [bs][out position]
__device__ int g_count;

__constant__ int c_off[17] = {0,1023,1982,2877,3708,4475,5178,5817,6392,6903,
                              7350,7733,8052,8307,8498,8625,8688};

__global__ __launch_bounds__(256, 2) void amps_main(const float* __restrict__ data,
                                                    const float* __restrict__ tri) {
    __shared__ unsigned ssel[NN];
    __shared__ float4 sm[8 * 264];   // per warp: 4 groups * 66 float4 (8 steps * 8 slots + skew)

    const int tid = threadIdx.x, warp = tid >> 5, lane = tid & 31;
    const int g = lane >> 3, bs = lane & 7;

    if (blockIdx.x == 0 && tid == 0) g_count = 0;   // reset for combine (kernel-order visible)

    // block-local selector bits: bit bs of ssel[m] = plane (0 if data!=0 else 1)
    for (int m = tid; m < NN; m += 256) {
        unsigned s = 0;
#pragma unroll
        for (int b = 0; b < 8; b++) s |= ((data[b * NN + m] != 0.0f) ? 0u : 1u) << b;
        ssel[m] = s;
    }
    __syncthreads();

    float4* smw = sm + warp * 264 + g * 66;
    const float4* tri4 = (const float4*)tri;

    const int cid = (blockIdx.x * 8 + warp) * 4 + g;
    const bool valid = (cid < NCID);
    const int cc = valid ? cid : 0;
    int c = 0;
#pragma unroll
    for (int j = 1; j < 16; j++) if (cc >= c_off[j]) c = j;
    const int n = 64 * c + (cc - c_off[c]);
    const int mS = 64 * c;
    const int mE = min(n, mS + SMCH - 1);
    const int steps = mE - mS + 1;
    const int ws = __reduce_max_sync(FULLM, steps);
    const size_t t0 = (size_t)n * (n + 1) / 2;
    const float4* base = tri4 + (t0 + mS) * 8;
    const int sc = steps - 1;

    float P[16];
#pragma unroll
    for (int q = 0; q < 16; q++) P[q] = (q % 5 == 0) ? 1.0f : 0.0f;

    float4 r[TT];
#pragma unroll
    for (int t = 0; t < TT; t++) r[t] = __ldg(base + (size_t)min(t, sc) * 8 + bs);

    for (int st = 0; st < ws; st += TT) {
        __syncwarp();
#pragma unroll
        for (int t = 0; t < TT; t++) smw[t * 8 + bs] = r[t];
        __syncwarp();
        if (st + TT < ws) {
#pragma unroll
            for (int t = 0; t < TT; t++)
                r[t] = __ldg(base + (size_t)min(st + TT + t, sc) * 8 + bs);
        }
#pragma unroll
        for (int t = 0; t < TT; t++) {
            const int s = st + t;
            const unsigned sw = ssel[mS + s <= (NN - 1) ? mS + s : (NN - 1)];
            const bool p = (sw >> bs) & 1u;
            float a[16];
#pragma unroll
            for (int q = 0; q < 8; q++) {
                float4 w = smw[t * 8 + q];
                a[(q >> 1) * 4 + (q & 1) * 2]     = p ? w.y : w.x;
                a[(q >> 1) * 4 + (q & 1) * 2 + 1] = p ? w.w : w.z;
            }
            if (s < steps) {
#pragma unroll
                for (int i = 0; i < 4; i++) {
                    float q0 = P[i*4+0]*a[0] + P[i*4+1]*a[4] + P[i*4+2]*a[8]  + P[i*4+3]*a[12];
                    float q1 = P[i*4+0]*a[1] + P[i*4+1]*a[5] + P[i*4+2]*a[9]  + P[i*4+3]*a[13];
                    float q2 = P[i*4+0]*a[2] + P[i*4+1]*a[6] + P[i*4+2]*a[10] + P[i*4+3]*a[14];
                    float q3 = P[i*4+0]*a[3] + P[i*4+1]*a[7] + P[i*4+2]*a[11] + P[i*4+3]*a[15];
                    P[i*4+0] = q0; P[i*4+1] = q1; P[i*4+2] = q2; P[i*4+3] = q3;
                }
            }
        }
    }
    if (valid) {
        float4* dst = (float4*)&g_M[(size_t)cid * 128 + bs * 16];
#pragma unroll
        for (int i = 0; i < 4; i++)
            dst[i] = make_float4(P[i*4], P[i*4+1], P[i*4+2], P[i*4+3]);
    }
}

// ---------------- combine: v = row0(P_0) @ P_1 @ ...; lse; fused last-block reduce ----------------
__global__ __launch_bounds__(256) void amps_combine(const float* __restrict__ data,
                                                    const float* __restrict__ diag,
                                                    float* __restrict__ out) {
    const int warp = threadIdx.x >> 5, lane = threadIdx.x & 31;
    const int bs = lane >> 2, rr = lane & 3;
    const int n = blockIdx.x * 8 + warp;

    if (n < NCH) {
        float4 vv = *(const float4*)&g_M[(size_t)n * 128 + bs * 16];  // cid(n,0)=n, row 0
        float v0 = vv.x, v1 = vv.y, v2 = vv.z, v3 = vv.w;

        const int nch = (n >> 6) + 1;
        for (int c = 1; c < nch; c++) {
            const int cid = c_off[c] + n - 64 * c;
            const float* Mb = &g_M[(size_t)cid * 128 + bs * 16];
            float nv = v0 * Mb[rr] + v1 * Mb[4 + rr] + v2 * Mb[8 + rr] + v3 * Mb[12 + rr];
            int qb = lane & ~3;
            v0 = __shfl_sync(FULLM, nv, qb);
            v1 = __shfl_sync(FULLM, nv, qb + 1);
            v2 = __shfl_sync(FULLM, nv, qb + 2);
            v3 = __shfl_sync(FULLM, nv, qb + 3);
        }
        const float* dg = diag + (size_t)(n + 1) * 8;
        const int rp = rr & 1;
        float x = v0 * dg[rp] + v1 * dg[2 + rp] + v2 * dg[4 + rp] + v3 * dg[6 + rp];
        float x1 = __shfl_sync(FULLM, x, (lane & ~3) + 1);
        if (rr == 0) {
            float x0 = x;
            float mx = fmaxf(x0, x1);
            float lse = mx + log1pf(expf(-fabsf(x0 - x1)));
            bool p1 = (data[bs * NN + (n + 1)] == 0.0f);
            g_contrib[bs * 1024 + n + 1] = (p1 ? x1 : x0) - lse;
        }
    }

    // ---- last block reduces everything (deterministic order) ----
    __shared__ int sdone;
    __threadfence();
    __syncthreads();
    if (threadIdx.x == 0) sdone = (atomicAdd(&g_count, 1) == gridDim.x - 1) ? 1 : 0;
    __syncthreads();
    if (!sdone) return;
    __threadfence();

    const int rbs = threadIdx.x >> 5;   // warp = sample
    const int rl = threadIdx.x & 31;
    float acc = 0.0f;
    const float4* cb = (const float4*)(g_contrib + rbs * 1024);
#pragma unroll
    for (int it = 0; it < 8; it++) {
        float4 v = cb[it * 32 + rl];
        if (it == 0 && rl == 0) {
            float x0 = diag[0], x1 = diag[1];
            float mx = fmaxf(x0, x1);
            float lse = mx + log1pf(expf(-fabsf(x0 - x1)));
            v.x = ((data[rbs * NN] == 0.0f) ? x1 : x0) - lse;  // n=0 term
        }
        acc += v.x + v.y + v.z + v.w;
    }
#pragma unroll
    for (int o = 16; o; o >>= 1) acc += __shfl_xor_sync(FULLM, acc, o);
    if (rl == 0) out[rbs] = acc;
}

extern "C" void kernel_launch(void* const* d_in, const int* in_sizes, int n_in,
                              void* d_out, int out_size) {
    const float* data = (const float*)d_in[0];
    const float* tri  = (const float*)d_in[1];
    const float* diag = (const float*)d_in[2];
    float* out = (float*)d_out;

    amps_main<<<NBLK, 256>>>(data, tri);
    amps_combine<<<128, 256>>>(data, diag, out);
}